// round 17
// baseline (speedup 1.0000x reference)
#include <cuda_runtime.h>
#include <cstdint>
#include <math.h>

// Problem: V=2048, E=512, H=512, L=3, T=512, B=64 -> steps = 511
#define TSTEPS   511
#define NB       64
#define HID      512
#define GATES    2048
#define MREAL    32704            // 511*64
#define MPAD     32768            // padded rows (zeros)
#define VOCAB    2048

typedef unsigned long long ull;

// ---------------------------------------------------------------------------
// Packed f32x2 helpers (sm_103a). FFMA2 is double-rate (R14: GEMM 47 TF/s).
// R16 finding: each LDS.128 costs 4 smem-crossbar cycles (512B charged, no
// broadcast dedup) -> minimize LDS instruction count per FFMA2.
// ---------------------------------------------------------------------------
__device__ __forceinline__ void ffma2(ull& d, ull a, ull b) {
    asm("fma.rn.f32x2 %0, %1, %2, %0;" : "+l"(d) : "l"(a), "l"(b));
}
__device__ __forceinline__ ull pk(float x, float y) {
    ull r; asm("mov.b64 %0, {%1, %2};" : "=l"(r) : "f"(x), "f"(y)); return r;
}
__device__ __forceinline__ float2 unpk(ull p) {
    float x, y; asm("mov.b64 {%0, %1}, %2;" : "=f"(x), "=f"(y) : "l"(p));
    return make_float2(x, y);
}
__device__ __forceinline__ float psum(ull p) {
    float2 v = unpk(p); return v.x + v.y;
}
// 128-bit shared load -> two packed f32x2 operands
__device__ __forceinline__ void lds2(ull& a, ull& b, uint32_t addr) {
    asm volatile("ld.shared.v2.b64 {%0,%1}, [%2];"
                 : "=l"(a), "=l"(b) : "r"(addr));
}

// ---------------------------------------------------------------------------
// Static scratch (no allocations anywhere)
// ---------------------------------------------------------------------------
__device__ float g_x [(size_t)MPAD * HID];    //  64 MB layer activations
__device__ float g_xg[(size_t)MPAD * GATES];  // 256 MB input gates / logits stage
// h state double buffer, quad-interleaved: h[k][b] at [(k>>2)*256 + b*4 + (k&3)]
__device__ float g_hbuf[2][HID * NB];
// 4 independent barrier groups (one per 16-batch group; batches don't couple)
__device__ unsigned g_bar_cnt[4];
__device__ volatile unsigned g_bar_gen[4];

// ---------------------------------------------------------------------------
// Embedding gather: x[m][:] = emb[tok[m]][:], zero for pad rows
// ---------------------------------------------------------------------------
__global__ void embed_kernel(const int* __restrict__ tok,
                             const float* __restrict__ emb,
                             float* __restrict__ x)
{
    int idx = blockIdx.x * blockDim.x + threadIdx.x;  // over MPAD*128 float4
    int m  = idx >> 7;
    int e4 = idx & 127;
    float4 v = make_float4(0.f, 0.f, 0.f, 0.f);
    if (m < MREAL) {
        int t = tok[m];
        v = ((const float4*)emb)[(size_t)t * 128 + e4];
    }
    ((float4*)x)[(size_t)m * 128 + e4] = v;
}

// ---------------------------------------------------------------------------
// GEMM + bias (unchanged from R14/R16 pass): BM=BN=128, BK=16, double-buffered,
// packed f32x2 accumulators, stride 136.
// ---------------------------------------------------------------------------
__global__ __launch_bounds__(256, 2)
void gemm_bias(const float* __restrict__ A, const float* __restrict__ W,
               const float* __restrict__ bias1, const float* __restrict__ bias2,
               float* __restrict__ C, int Mguard)
{
    __shared__ float As[2][16][136];
    __shared__ float Ws[2][16][136];
    const int tid = threadIdx.x;
    const int tx = tid & 15;
    const int ty = tid >> 4;
    const int n0 = blockIdx.x * 128;
    const int m0 = blockIdx.y * 128;

    ull acc2[8][4];
#pragma unroll
    for (int i = 0; i < 8; ++i)
#pragma unroll
        for (int jp = 0; jp < 4; ++jp) acc2[i][jp] = 0ull;

    const float* Ap = A + (size_t)m0 * 512;
    const float* Wp = W + (size_t)n0 * 512;

    const int r0  = tid >> 2;
    const int r1  = (tid + 256) >> 2;
    const int kq0 = (tid & 3) << 2;

    float4 pa0 = *(const float4*)(Ap + (size_t)r0 * 512 + kq0);
    float4 pa1 = *(const float4*)(Ap + (size_t)r1 * 512 + kq0);
    float4 pw0 = *(const float4*)(Wp + (size_t)r0 * 512 + kq0);
    float4 pw1 = *(const float4*)(Wp + (size_t)r1 * 512 + kq0);

    As[0][kq0 + 0][r0] = pa0.x; As[0][kq0 + 1][r0] = pa0.y;
    As[0][kq0 + 2][r0] = pa0.z; As[0][kq0 + 3][r0] = pa0.w;
    As[0][kq0 + 0][r1] = pa1.x; As[0][kq0 + 1][r1] = pa1.y;
    As[0][kq0 + 2][r1] = pa1.z; As[0][kq0 + 3][r1] = pa1.w;
    Ws[0][kq0 + 0][r0] = pw0.x; Ws[0][kq0 + 1][r0] = pw0.y;
    Ws[0][kq0 + 2][r0] = pw0.z; Ws[0][kq0 + 3][r0] = pw0.w;
    Ws[0][kq0 + 0][r1] = pw1.x; Ws[0][kq0 + 1][r1] = pw1.y;
    Ws[0][kq0 + 2][r1] = pw1.z; Ws[0][kq0 + 3][r1] = pw1.w;
    __syncthreads();

    for (int it = 0; it < 32; ++it) {
        const int cur = it & 1;
        const int nxt = cur ^ 1;

        if (it < 31) {
            int kn = (it + 1) * 16 + kq0;
            pa0 = *(const float4*)(Ap + (size_t)r0 * 512 + kn);
            pa1 = *(const float4*)(Ap + (size_t)r1 * 512 + kn);
            pw0 = *(const float4*)(Wp + (size_t)r0 * 512 + kn);
            pw1 = *(const float4*)(Wp + (size_t)r1 * 512 + kn);
        }

#pragma unroll
        for (int kk = 0; kk < 16; ++kk) {
            float4 a0 = *(const float4*)&As[cur][kk][ty * 8];
            float4 a1 = *(const float4*)&As[cur][kk][ty * 8 + 4];
            float4 w0 = *(const float4*)&Ws[cur][kk][tx * 8];
            float4 w1 = *(const float4*)&Ws[cur][kk][tx * 8 + 4];
            ull wp[4] = { pk(w0.x, w0.y), pk(w0.z, w0.w),
                          pk(w1.x, w1.y), pk(w1.z, w1.w) };
            ull ad[8] = { pk(a0.x, a0.x), pk(a0.y, a0.y),
                          pk(a0.z, a0.z), pk(a0.w, a0.w),
                          pk(a1.x, a1.x), pk(a1.y, a1.y),
                          pk(a1.z, a1.z), pk(a1.w, a1.w) };
#pragma unroll
            for (int i = 0; i < 8; ++i)
#pragma unroll
                for (int jp = 0; jp < 4; ++jp)
                    ffma2(acc2[i][jp], ad[i], wp[jp]);
        }

        if (it < 31) {
            As[nxt][kq0 + 0][r0] = pa0.x; As[nxt][kq0 + 1][r0] = pa0.y;
            As[nxt][kq0 + 2][r0] = pa0.z; As[nxt][kq0 + 3][r0] = pa0.w;
            As[nxt][kq0 + 0][r1] = pa1.x; As[nxt][kq0 + 1][r1] = pa1.y;
            As[nxt][kq0 + 2][r1] = pa1.z; As[nxt][kq0 + 3][r1] = pa1.w;
            Ws[nxt][kq0 + 0][r0] = pw0.x; Ws[nxt][kq0 + 1][r0] = pw0.y;
            Ws[nxt][kq0 + 2][r0] = pw0.z; Ws[nxt][kq0 + 3][r0] = pw0.w;
            Ws[nxt][kq0 + 0][r1] = pw1.x; Ws[nxt][kq0 + 1][r1] = pw1.y;
            Ws[nxt][kq0 + 2][r1] = pw1.z; Ws[nxt][kq0 + 3][r1] = pw1.w;
            __syncthreads();
        }
    }

    float bb[8];
#pragma unroll
    for (int j = 0; j < 8; ++j) {
        int n = n0 + tx * 8 + j;
        bb[j] = bias1[n] + (bias2 ? bias2[n] : 0.0f);
    }
#pragma unroll
    for (int i = 0; i < 8; ++i) {
        int m = m0 + ty * 8 + i;
        if (m < Mguard) {
            float* cp = C + (size_t)m * 2048 + n0 + tx * 8;
            float2 p0 = unpk(acc2[i][0]), p1 = unpk(acc2[i][1]);
            float2 p2 = unpk(acc2[i][2]), p3 = unpk(acc2[i][3]);
            float4 v0 = make_float4(p0.x + bb[0], p0.y + bb[1],
                                    p1.x + bb[2], p1.y + bb[3]);
            float4 v1 = make_float4(p2.x + bb[4], p2.y + bb[5],
                                    p3.x + bb[6], p3.y + bb[7]);
            *(float4*)cp       = v0;
            *(float4*)(cp + 4) = v1;
        }
    }
}

// ---------------------------------------------------------------------------
// Persistent LSTM layer, K-SPLIT MICROTILE (R17):
// 128 blocks = 4 b-groups x 32 j-groups. Block = 16 b x 16 j, 256 threads.
// Main loop thread = (cg, ks): cg = tid>>2 covers (4 batches x 1 j x 4 gates),
// ks = tid&3 covers k-range [ks*128, ks*128+128).
// Per k4: 4 h LDS.128 + 4 w LDS.128 = 8 loads for 32 FFMA2 (1 crossbar
// cyc/FFMA2, was 2.5). Partials in smem (16 KB), reduced once per step.
// smem: hs float4[128][16] (32KB) + Wsm float4[128][4][16] (128KB)
//     + spart float[4][64][4][4] (16KB) = 176 KB.
// Barrier: per-b-group (32 blocks), 4 independent groups.
// ---------------------------------------------------------------------------
__global__ void lstm_layer(const float* __restrict__ xg,
                           const float* __restrict__ Whh,
                           float* __restrict__ xout)
{
    extern __shared__ float sm[];
    float* hs    = sm;            // float4[128][16]     = 32 KB
    float* Wsm   = sm + 8192;     // float4[128][4][16]  = 128 KB
    float* spart = sm + 40960;    // float[ks][cg][g][bi] = 16 KB

    const int tid = threadIdx.x;
    const int bk  = blockIdx.x;
    const int grp = bk & 3;
    const int b0  = grp * 16;
    const int j0  = (bk >> 2) * 16;

    // main-loop mapping
    const int ks  = tid & 3;
    const int cg  = tid >> 2;          // 0..63
    const int jjm = cg >> 2;           // 0..15
    const int b4  = (cg & 3) * 4;      // 0,4,8,12

    // pointwise mapping (one thread per cell)
    const int bl = tid & 15;
    const int jl = tid >> 4;           // 0..15
    const int j  = j0 + jl;
    const int b  = b0 + bl;
    const int pcg = jl * 4 + (bl >> 2);
    const int pbi = bl & 3;

    // Load W_hh slice: Wsm[k4][g][j2] = Whh[(g*512 + j0 + j2)][4k4..4k4+3]
    for (int idx = tid; idx < 128 * 4 * 16; idx += 256) {
        int k4 = idx & 127;
        int g  = (idx >> 7) & 3;
        int j2 = idx >> 9;
        ((float4*)Wsm)[(k4 * 4 + g) * 16 + j2] =
            ((const float4*)Whh)[(size_t)(g * 512 + j0 + j2) * 128 + k4];
    }
    // h0 = 0
    for (int idx = tid; idx < 2048; idx += 256)
        ((float4*)hs)[idx] = make_float4(0.f, 0.f, 0.f, 0.f);
    __syncthreads();

    uint32_t smem_base;
    asm("{ .reg .u64 t; cvta.to.shared.u64 t, %1; cvt.u32.u64 %0, t; }"
        : "=r"(smem_base) : "l"(sm));
    const uint32_t ha = smem_base + (uint32_t)b4 * 16u;            // + k4*256
    const uint32_t wa = smem_base + 32768u + (uint32_t)jjm * 16u;  // + (k4*4+g)*256

    // h output slot (quad-interleaved global layout)
    const int hoff = (j >> 2) * 256 + b * 4 + (j & 3);

    // preload step-0 gate inputs (pointwise mapping)
    size_t base0 = ((size_t)b) * 2048 + (size_t)j;
    float xi  = xg[base0];
    float xf  = xg[base0 + 512];
    float xgg = xg[base0 + 1024];
    float xo  = xg[base0 + 1536];

    float c = 0.f;
    for (int t = 0; t < TSTEPS; ++t) {
        // ---- k-split partial dot products ----
        ull acc[4][4];
#pragma unroll
        for (int g = 0; g < 4; ++g)
#pragma unroll
            for (int bi = 0; bi < 4; ++bi) acc[g][bi] = 0ull;

#pragma unroll 4
        for (int kk = 0; kk < 32; ++kk) {
            int k4 = ks * 32 + kk;
            uint32_t hb = ha + (uint32_t)k4 * 256u;
            ull h0, h1, h2, h3, h4, h5, h6, h7;
            lds2(h0, h1, hb);
            lds2(h2, h3, hb + 16u);
            lds2(h4, h5, hb + 32u);
            lds2(h6, h7, hb + 48u);
            uint32_t wb = wa + (uint32_t)k4 * 1024u;
#pragma unroll
            for (int g = 0; g < 4; ++g) {
                ull w0, w1;
                lds2(w0, w1, wb + (uint32_t)g * 256u);
                ffma2(acc[g][0], h0, w0); ffma2(acc[g][0], h1, w1);
                ffma2(acc[g][1], h2, w0); ffma2(acc[g][1], h3, w1);
                ffma2(acc[g][2], h4, w0); ffma2(acc[g][2], h5, w1);
                ffma2(acc[g][3], h6, w0); ffma2(acc[g][3], h7, w1);
            }
        }

        // write partials: spart[ks][cg][g][bi]
        float4* sp4 = (float4*)spart;
#pragma unroll
        for (int g = 0; g < 4; ++g) {
            float4 v = make_float4(psum(acc[g][0]), psum(acc[g][1]),
                                   psum(acc[g][2]), psum(acc[g][3]));
            sp4[(ks * 64 + cg) * 4 + g] = v;
        }
        __syncthreads();

        // ---- reduce 4 k-splits + pointwise LSTM cell ----
        float sg[4];
#pragma unroll
        for (int g = 0; g < 4; ++g) {
            sg[g] = spart[((0 * 64 + pcg) * 4 + g) * 4 + pbi]
                  + spart[((1 * 64 + pcg) * 4 + g) * 4 + pbi]
                  + spart[((2 * 64 + pcg) * 4 + g) * 4 + pbi]
                  + spart[((3 * 64 + pcg) * 4 + g) * 4 + pbi];
        }

        float I = 1.f / (1.f + expf(-(xi + sg[0])));
        float F = 1.f / (1.f + expf(-(xf + sg[1])));
        float G = tanhf(xgg + sg[2]);
        float O = 1.f / (1.f + expf(-(xo + sg[3])));
        c = F * c + I * G;
        float h = O * tanhf(c);

        xout[((size_t)t * 64 + b) * 512 + j] = h;
        int wb2 = (t + 1) & 1;
        g_hbuf[wb2][hoff] = h;

        // prefetch next step's gate inputs (hidden under barrier + reload)
        if (t + 1 < TSTEPS) {
            size_t nb_ = ((size_t)(t + 1) * 64 + b) * 2048 + (size_t)j;
            xi  = xg[nb_];
            xf  = xg[nb_ + 512];
            xgg = xg[nb_ + 1024];
            xo  = xg[nb_ + 1536];
        }

        // ---- per-b-group grid barrier (32 blocks; monotonic generation) ----
        __syncthreads();
        if (tid == 0) {
            unsigned gen = g_bar_gen[grp];
            __threadfence();
            if (atomicAdd(&g_bar_cnt[grp], 1u) == 31u) {
                g_bar_cnt[grp] = 0;
                __threadfence();
                g_bar_gen[grp] = gen + 1u;
            } else {
                while (g_bar_gen[grp] == gen) { }
            }
            __threadfence();
        }
        __syncthreads();

        // reload h tile: this block's 16 batches, all 512 k (32 KB)
        {
            const float4* src = (const float4*)g_hbuf[wb2];
            for (int idx = tid; idx < 2048; idx += 256) {
                int k4  = idx >> 4;
                int bl2 = idx & 15;
                ((float4*)hs)[idx] = src[k4 * 64 + b0 + bl2];
            }
        }
        __syncthreads();
    }
}

// ---------------------------------------------------------------------------
// threefry2x32 (JAX), key = (0, 1)
// ---------------------------------------------------------------------------
__device__ __forceinline__ void threefry01(uint32_t x0, uint32_t x1,
                                           uint32_t& o0, uint32_t& o1)
{
    const uint32_t k0 = 0u, k1 = 1u;
    const uint32_t k2 = 0x1BD11BDAu ^ k0 ^ k1;   // 0x1BD11BDB
    x0 += k0; x1 += k1;
#define TFR(r) { x0 += x1; x1 = (x1 << (r)) | (x1 >> (32 - (r))); x1 ^= x0; }
    TFR(13) TFR(15) TFR(26) TFR(6)
    x0 += k1; x1 += k2 + 1u;
    TFR(17) TFR(29) TFR(16) TFR(24)
    x0 += k2; x1 += k0 + 2u;
    TFR(13) TFR(15) TFR(26) TFR(6)
    x0 += k0; x1 += k1 + 3u;
    TFR(17) TFR(29) TFR(16) TFR(24)
    x0 += k1; x1 += k2 + 4u;
    TFR(13) TFR(15) TFR(26) TFR(6)
    x0 += k2; x1 += k0 + 5u;
#undef TFR
    o0 = x0; o1 = x1;
}

// JAX gumbel: u = bitcast(bits>>9 | 0x3f800000) - 1; u = max(u, tiny);
// g = -log(-log(u)).  Accurate logf required (fast-log tail error flips argmax).
__device__ __forceinline__ float gumbelf(uint32_t bits)
{
    float u = __uint_as_float((bits >> 9) | 0x3f800000u) - 1.0f;
    u = fmaxf(u, 1.17549435e-38f);
    return -logf(-logf(u));
}

// Partitionable threefry random_bits (jax/_src/prng.py):
//   bits1, bits2 = threefry2x32(key, counts_hi=0, counts_lo=i)
//   bit_width < 64: convert(bits1 ^ bits2)   <-- XOR of both output words
// One block per (t,b) row; 256 threads scan the 2048-vocab gumbel-argmax.
__global__ void sample_kernel(const float* __restrict__ logits,
                              float* outF, int* outI, int asInt)
{
    const int r = blockIdx.x;
    const int tid = threadIdx.x;

    float best = -3.4e38f;
    int bidx = 0;
    for (int v = tid; v < VOCAB; v += 256) {
        uint32_t i = (uint32_t)r * 2048u + (uint32_t)v;   // linear index < 2^32
        uint32_t o0, o1;
        threefry01(0u, i, o0, o1);
        float val = logits[(size_t)r * 2048 + v] + gumbelf(o0 ^ o1);
        if (val > best) { best = val; bidx = v; }   // strided v increasing -> first idx
    }

    __shared__ float svv[256];
    __shared__ int   sii[256];
    svv[tid] = best; sii[tid] = bidx;
    __syncthreads();
    for (int s = 128; s > 0; s >>= 1) {
        if (tid < s) {
            float v2 = svv[tid + s]; int i2 = sii[tid + s];
            float v1 = svv[tid];     int i1 = sii[tid];
            if (v2 > v1 || (v2 == v1 && i2 < i1)) { svv[tid] = v2; sii[tid] = i2; }
        }
        __syncthreads();
    }
    if (tid == 0) {
        if (asInt) outI[r] = sii[0];
        else       outF[r] = (float)sii[0];
    }
}

// ---------------------------------------------------------------------------
// Launch
// ---------------------------------------------------------------------------
extern "C" void kernel_launch(void* const* d_in, const int* in_sizes, int n_in,
                              void* d_out, int out_size)
{
    const int*   tok  = (const int*)  d_in[0];
    const float* emb  = (const float*)d_in[1];
    const float* Wih  = (const float*)d_in[2];
    const float* Whh  = (const float*)d_in[3];
    const float* bih  = (const float*)d_in[4];
    const float* bhh  = (const float*)d_in[5];
    const float* Wout = (const float*)d_in[6];
    const float* bout = (const float*)d_in[7];

    void* p;
    cudaGetSymbolAddress(&p, g_x);   float* xbuf  = (float*)p;
    cudaGetSymbolAddress(&p, g_xg);  float* xgbuf = (float*)p;

    cudaFuncSetAttribute(lstm_layer,
                         cudaFuncAttributeMaxDynamicSharedMemorySize, 180224);

    embed_kernel<<<MPAD * 128 / 256, 256>>>(tok, emb, xbuf);

    dim3 gg(GATES / 128, MPAD / 128);
    for (int l = 0; l < 3; ++l) {
        gemm_bias<<<gg, 256>>>(xbuf, Wih + (size_t)l * GATES * HID,
                               bih + l * GATES, bhh + l * GATES, xgbuf, MPAD);
        lstm_layer<<<128, 256, 180224>>>(xgbuf, Whh + (size_t)l * GATES * HID, xbuf);
    }

    // Output dispatch: tuple (indices, logits) flattened is the expected case.
    float* logitsPtr;
    int mode;                               // 0 full, 1 logits-only, 2 int idx
    if (out_size == MREAL + MREAL * VOCAB) { mode = 0; logitsPtr = (float*)d_out + MREAL; }
    else if (out_size == MREAL)            { mode = 2; logitsPtr = xgbuf; }
    else                                   { mode = 1; logitsPtr = (float*)d_out; }

    gemm_bias<<<gg, 256>>>(xbuf, Wout, bout, nullptr, logitsPtr, MREAL);

    if (mode == 0)
        sample_kernel<<<MREAL, 256>>>(logitsPtr, (float*)d_out, nullptr, 0);
    else if (mode == 2)
        sample_kernel<<<MREAL, 256>>>(logitsPtr, nullptr, (int*)d_out, 1);
}